// round 15
// baseline (speedup 1.0000x reference)
#include <cuda_runtime.h>
#include <cuda_fp16.h>
#include <cstdint>

#define NN   4096
#define UU   2048
#define RR   5
#define BB   30
#define HH0  500
#define HH1  75
#define EE   262144
#define LDG2 512
#define LDS2 80           // padded d_sums / g2-block stride
#define KT   64           // GEMM2 k-tiles (K=4096, 64 halves per tile)
#define KPW  16           // gemmW k-tiles (K=512, 32 halves per tile)
#define NP   80           // gemmW N extent (75 padded to 80)
#define WSTR 80           // gemmW A/B smem row stride bytes (conflict-free LDS.32)
#define STGW_B (128 * WSTR + NP * WSTR)   // 16640 bytes per stage
#define NSEG (NN * RR)    // 20480 segments

// ---------------- scratch (device globals; no allocation allowed) ----------
__device__ __half d_fch[128 * 512];                 // fc_w fp16, natural order
__device__ __half d_xp[(size_t)NN * NN];            // x fp16 + k-permuted(16)
__device__ __half d_Wp[(size_t)6 * NN * 512];       // W fp16 [6*4096][512] (blk5=root)
__device__ __half d_VTp[(size_t)LDG2 * NN];         // V^T fp16+perm; row 80r+j; pad 0
__device__ float  d_g2[(size_t)NN * LDG2];          // g[n][80r+j]
__device__ float  d_sums[(size_t)NSEG * LDS2];
__device__ float  d_cnt[NSEG];
__device__ float  d_biasV[HH1];
__device__ int    d_i64flag[2];
// edge sort scratch
__device__ int d_hcnt[NSEG];
__device__ int d_bsum[160];
__device__ int d_bbase[160];
__device__ int d_base[NSEG];
__device__ int d_wptr[NSEG];
__device__ int d_eidx[EE];

// ---------------- small helpers --------------------------------------------
__device__ __forceinline__ uint32_t smem_u32(const void* p) {
    uint32_t a;
    asm("{ .reg .u64 t; cvta.to.shared.u64 t, %1; cvt.u32.u64 %0, t; }"
        : "=r"(a) : "l"(p));
    return a;
}
__device__ __forceinline__ uint32_t packh2(float a, float b) {
    __half2 h = __floats2half2_rn(a, b);
    return *reinterpret_cast<uint32_t*>(&h);
}
#define CP_ASYNC16(dst, src) \
    asm volatile("cp.async.cg.shared.global [%0], [%1], 16;" :: "r"(dst), "l"(src))
#define CP_COMMIT() asm volatile("cp.async.commit_group;" ::: "memory")

__device__ __forceinline__ void edge_seg(const unsigned int* ei,
                                         const unsigned int* et, int e,
                                         int& src, int& seg) {
    long long s, d, t;
    if (d_i64flag[0]) {
        s = reinterpret_cast<const long long*>(ei)[e];
        d = reinterpret_cast<const long long*>(ei)[EE + e];
    } else {
        s = reinterpret_cast<const int*>(ei)[e];
        d = reinterpret_cast<const int*>(ei)[EE + e];
    }
    t = d_i64flag[1] ? reinterpret_cast<const long long*>(et)[e]
                     : (long long)reinterpret_cast<const int*>(et)[e];
    src = (int)s;
    seg = (int)d * RR + (int)t;
}

// ---------------- fused prep: xp(uint4) + detect + hist-zero + fch + biasV ---
// xp permute in 16-groups: stored[p] <- k where
//   stored pairs for even half: (k0,k1),(k8,k9),(k2,k3),(k10,k11)
//   stored pairs for odd half:  (k4,k5),(k12,k13),(k6,k7),(k14,k15)
__global__ void k_prep(const float* __restrict__ x,
                       const float* __restrict__ fc_w,
                       const float* __restrict__ bias,
                       const unsigned int* __restrict__ ei,
                       const unsigned int* __restrict__ et) {
    int idx = blockIdx.x * blockDim.x + threadIdx.x;   // over NN*NN/8

    {   // xp: 8 halves (one uint4 store) per thread
        int row = idx >> 9;                 // NN/8 = 512 stores per row
        int g = idx & 511;
        const float* xr = x + (size_t)row * NN + (g >> 1) * 16 + (g & 1) * 4;
        float4 vlo = *reinterpret_cast<const float4*>(xr);
        float4 vhi = *reinterpret_cast<const float4*>(xr + 8);
        uint4 o;
        o.x = packh2(vlo.x, vlo.y);
        o.y = packh2(vhi.x, vhi.y);
        o.z = packh2(vlo.z, vlo.w);
        o.w = packh2(vhi.z, vhi.w);
        *reinterpret_cast<uint4*>(d_xp + ((size_t)row * NN + g * 8)) = o;
    }
    if (idx < 128 * 512) {                 // fch: fp16, natural order, zero pad
        int n = idx >> 9, k = idx & 511;
        float v = (n < HH1 && k < HH0) ? fc_w[n * HH0 + k] : 0.f;
        d_fch[idx] = __float2half_rn(v);
    }
    if (idx < NSEG) d_hcnt[idx] = 0;
    if (idx < HH1) {                       // biasV
        float s = 0.f;
        const float* fw = fc_w + idx * HH0;
        for (int o = 0; o < HH0; o++) s = fmaf(bias[o], fw[o], s);
        d_biasV[idx] = s;
    }
    if (blockIdx.x == 0 && threadIdx.x < 64) {
        int w = threadIdx.x >> 5, lane = threadIdx.x & 31;
        unsigned v = (w == 0) ? ei[2 * lane + 1] : et[2 * lane + 1];
        unsigned b = __ballot_sync(0xFFFFFFFFu, v != 0u);
        if (lane == 0) d_i64flag[w] = (b == 0u);
    }
}

// ---------------- buildW (float4): Wp = fp16(comp x basis), + root, + pad ----
__global__ void k_buildW(const float* __restrict__ basis,
                         const float* __restrict__ root,
                         const float* __restrict__ comp) {
    __shared__ float sc[RR * BB];
    if (threadIdx.x < RR * BB) sc[threadIdx.x] = comp[threadIdx.x];
    __syncthreads();
    int idx = blockIdx.x * blockDim.x + threadIdx.x;   // over NN*125
    if (idx >= NN * 125) return;
    int i = idx / 125, o4 = idx - i * 125;             // o = o4*4
    size_t src_off = (size_t)i * HH0 + o4 * 4;

    float4 acc[RR];
#pragma unroll
    for (int r = 0; r < RR; r++) acc[r] = make_float4(0.f, 0.f, 0.f, 0.f);
#pragma unroll 5
    for (int b = 0; b < BB; b++) {
        float4 v = *reinterpret_cast<const float4*>(
            basis + (size_t)b * (NN * HH0) + src_off);
#pragma unroll
        for (int r = 0; r < RR; r++) {
            float cc = sc[r * BB + b];
            acc[r].x = fmaf(cc, v.x, acc[r].x);
            acc[r].y = fmaf(cc, v.y, acc[r].y);
            acc[r].z = fmaf(cc, v.z, acc[r].z);
            acc[r].w = fmaf(cc, v.w, acc[r].w);
        }
    }
#pragma unroll
    for (int r = 0; r < RR; r++) {
        uint2 o;
        o.x = packh2(acc[r].x, acc[r].y);
        o.y = packh2(acc[r].z, acc[r].w);
        *reinterpret_cast<uint2*>(d_Wp + (((size_t)(r * NN + i)) << 9) + o4 * 4) = o;
    }
    {
        float4 rv = *reinterpret_cast<const float4*>(root + src_off);
        uint2 o;
        o.x = packh2(rv.x, rv.y);
        o.y = packh2(rv.z, rv.w);
        *reinterpret_cast<uint2*>(d_Wp + (((size_t)(RR * NN + i)) << 9) + o4 * 4) = o;
    }
    // zero-pad o = 500..511 for all 6*NN rows: 3 x uint2 (4 halves) per row
    if (idx < 6 * NN * 3) {
        int row = idx / 3, q = idx - row * 3;
        uint2 z = make_uint2(0u, 0u);
        *reinterpret_cast<uint2*>(d_Wp + ((size_t)row << 9) + 500 + q * 4) = z;
    }
}

// ---------------- edge sort: histogram ---------------------------------------
__global__ void k_hist(const unsigned int* __restrict__ ei,
                       const unsigned int* __restrict__ et) {
    int e = blockIdx.x * blockDim.x + threadIdx.x;
    if (e >= EE) return;
    int src, seg;
    edge_seg(ei, et, e, src, seg);
    atomicAdd(&d_hcnt[seg], 1);
}

// ---------------- scan stage 1 ------------------------------------------------
__global__ void k_scan1() {
    int tid = threadIdx.x;
    int i = blockIdx.x * 128 + tid;
    int lane = tid & 31, w = tid >> 5;
    int v = d_hcnt[i];
    int x = v;
#pragma unroll
    for (int o = 1; o < 32; o <<= 1) {
        int y = __shfl_up_sync(0xFFFFFFFFu, x, o);
        if (lane >= o) x += y;
    }
    __shared__ int ws[4], we[4];
    if (lane == 31) ws[w] = x;
    __syncthreads();
    if (tid == 0) {
        int run = 0;
        for (int k = 0; k < 4; k++) { we[k] = run; run += ws[k]; }
        d_bsum[blockIdx.x] = run;
    }
    __syncthreads();
    d_base[i] = (x - v) + we[w];
}

// ---------------- scan stage 2 ------------------------------------------------
__global__ void k_scan2() {
    int tid = threadIdx.x;   // 256
    int lane = tid & 31, w = tid >> 5;
    int v = (tid < 160) ? d_bsum[tid] : 0;
    int x = v;
#pragma unroll
    for (int o = 1; o < 32; o <<= 1) {
        int y = __shfl_up_sync(0xFFFFFFFFu, x, o);
        if (lane >= o) x += y;
    }
    __shared__ int ws[8], we[8];
    if (lane == 31) ws[w] = x;
    __syncthreads();
    if (tid == 0) {
        int run = 0;
        for (int k = 0; k < 8; k++) { we[k] = run; run += ws[k]; }
    }
    __syncthreads();
    if (tid < 160) d_bbase[tid] = (x - v) + we[w];
}

// ---------------- scan stage 3 ------------------------------------------------
__global__ void k_scan3() {
    int i = blockIdx.x * blockDim.x + threadIdx.x;
    if (i >= NSEG) return;
    int b = d_base[i] + d_bbase[i >> 7];
    d_base[i] = b;
    d_wptr[i] = b;
    d_cnt[i] = (float)d_hcnt[i];
}

// ---------------- scatter: CSR fill ------------------------------------------
__global__ void k_scatter(const unsigned int* __restrict__ ei,
                          const unsigned int* __restrict__ et) {
    int e = blockIdx.x * blockDim.x + threadIdx.x;
    if (e >= EE) return;
    int src, seg;
    edge_seg(ei, et, e, src, seg);
    int pos = atomicAdd(&d_wptr[seg], 1);
    d_eidx[pos] = src;
}

// ---------------- gemmW (TC fp16): VTp = (Wp @ fch^T)^T, M=24576, N=80 -------
__global__ void __launch_bounds__(256, 2) gemmW() {
    extern __shared__ char smc[];
    uint32_t smb = smem_u32(smc);
    int tid = threadIdx.x;
    int lane = tid & 31, wid = tid >> 5;
    int wm = wid & 3, wn = wid >> 2;     // 4 x 2 warps: 32(M) x 40(N)
    int m0 = blockIdx.y * 128;
    const __half* Ag = d_Wp + ((size_t)m0 << 9);

    float acc[2][5][4];
#pragma unroll
    for (int a = 0; a < 2; a++)
#pragma unroll
        for (int b = 0; b < 5; b++)
#pragma unroll
            for (int d = 0; d < 4; d++) acc[a][b][d] = 0.f;

    auto load_stage = [&](int s, int k0) {   // k0 in halves (32 per tile)
        uint32_t base = smb + (uint32_t)s * STGW_B;
#pragma unroll
        for (int i = 0; i < 2; i++) {        // A: 128 rows x 4 chunks of 16B
            int idx = tid + i * 256;
            int row = idx >> 2, m = idx & 3;
            CP_ASYNC16(base + row * WSTR + m * 16,
                       Ag + ((size_t)row << 9) + k0 + m * 8);
        }
#pragma unroll
        for (int i = 0; i < 2; i++) {        // B: 80 rows x 4 chunks of 16B
            int idx = tid + i * 256;
            if (idx < NP * 4) {
                int row = idx >> 2, m = idx & 3;
                CP_ASYNC16(base + 128 * WSTR + row * WSTR + m * 16,
                           d_fch + ((size_t)row << 9) + k0 + m * 8);
            }
        }
    };

    load_stage(0, 0);  CP_COMMIT();
    load_stage(1, 32); CP_COMMIT();
    load_stage(2, 64); CP_COMMIT();

    const int r = lane >> 2, c = lane & 3;

    for (int kt = 0; kt < KPW; kt++) {
        int s = kt & 3;
        asm volatile("cp.async.wait_group 2;" ::: "memory");
        __syncthreads();
        if (kt + 3 < KPW) load_stage((kt + 3) & 3, (kt + 3) * 32);
        CP_COMMIT();

        const char* Asf = smc + (size_t)s * STGW_B;
        const char* Bsf = Asf + 128 * WSTR;
#pragma unroll
        for (int kk = 0; kk < 2; kk++) {      // 2 k-steps of K=16
            uint32_t a0[2], a1[2], a2[2], a3[2];
#pragma unroll
            for (int mt = 0; mt < 2; mt++) {
                int ro = wm * 32 + mt * 16 + r;
                a0[mt] = *reinterpret_cast<const uint32_t*>(Asf + ro * WSTR + (8 * kk + c) * 4);
                a2[mt] = *reinterpret_cast<const uint32_t*>(Asf + ro * WSTR + (8 * kk + 4 + c) * 4);
                a1[mt] = *reinterpret_cast<const uint32_t*>(Asf + (ro + 8) * WSTR + (8 * kk + c) * 4);
                a3[mt] = *reinterpret_cast<const uint32_t*>(Asf + (ro + 8) * WSTR + (8 * kk + 4 + c) * 4);
            }
#pragma unroll
            for (int nt = 0; nt < 5; nt++) {
                int n = wn * 40 + nt * 8 + r;
                uint32_t b0 = *reinterpret_cast<const uint32_t*>(
                    Bsf + n * WSTR + (8 * kk + c) * 4);
                uint32_t b1 = *reinterpret_cast<const uint32_t*>(
                    Bsf + n * WSTR + (8 * kk + 4 + c) * 4);
#pragma unroll
                for (int mt = 0; mt < 2; mt++) {
                    asm volatile(
                        "mma.sync.aligned.m16n8k16.row.col.f32.f16.f16.f32 "
                        "{%0,%1,%2,%3}, {%4,%5,%6,%7}, {%8,%9}, {%0,%1,%2,%3};"
                        : "+f"(acc[mt][nt][0]), "+f"(acc[mt][nt][1]),
                          "+f"(acc[mt][nt][2]), "+f"(acc[mt][nt][3])
                        : "r"(a0[mt]), "r"(a1[mt]), "r"(a2[mt]), "r"(a3[mt]),
                          "r"(b0), "r"(b1));
                }
            }
        }
    }

    // epilogue: VTp[(80*r5 + col)][perm16(i)] = fp16(acc)
#pragma unroll
    for (int mt = 0; mt < 2; mt++) {
        int m = m0 + wm * 32 + mt * 16 + r;
        int r5 = m >> 12;
        int i1 = m & 4095;
        int i2 = i1 + 8;
        int k1 = i1 & 15, k2 = i2 & 15;
        int pos1 = (i1 & ~15) | ((((k1 & 7) >> 1) << 2) | ((k1 >> 3) << 1) | (k1 & 1));
        int pos2 = (i2 & ~15) | ((((k2 & 7) >> 1) << 2) | ((k2 >> 3) << 1) | (k2 & 1));
#pragma unroll
        for (int nt = 0; nt < 5; nt++) {
            int col = wn * 40 + nt * 8 + 2 * c;
            if (col < HH1) {
                size_t vr = (size_t)(r5 * LDS2 + col) << 12;
                d_VTp[vr + pos1] = __float2half_rn(acc[mt][nt][0]);
                d_VTp[vr + pos2] = __float2half_rn(acc[mt][nt][2]);
            }
            if (col + 1 < HH1) {
                size_t vr = (size_t)(r5 * LDS2 + col + 1) << 12;
                d_VTp[vr + pos1] = __float2half_rn(acc[mt][nt][1]);
                d_VTp[vr + pos2] = __float2half_rn(acc[mt][nt][3]);
            }
        }
    }
}

// ---------------- GEMM2 (TC fp16 m16n8k16): g2 = xp @ VTp^T ------------------
#define STG_F 6144   // floats per stage: A 16KB + B 8KB

__global__ void __launch_bounds__(128, 2) gemm2_mma() {
    extern __shared__ float sm[];
    uint32_t smb = smem_u32(sm);
    int tid = threadIdx.x;             // 128 threads
    int lane = tid & 31, wid = tid >> 5;
    int wm = wid & 1, wn = wid >> 1;   // 4 warps: 2(M) x 2(N), 64x32 each
    int m0 = blockIdx.y * 128, n0 = blockIdx.x * 64;
    const __half* Ag = d_xp + (size_t)m0 * NN;
    const __half* Bg = d_VTp + (size_t)n0 * NN;

    float acc[4][4][4];
#pragma unroll
    for (int a = 0; a < 4; a++)
#pragma unroll
        for (int b = 0; b < 4; b++)
#pragma unroll
            for (int d = 0; d < 4; d++) acc[a][b][d] = 0.f;

    auto load_stage = [&](int s, int k0) {   // k0 in halves
        uint32_t base = smb + (uint32_t)s * (STG_F * 4);
#pragma unroll
        for (int i = 0; i < 8; i++) {        // A: 128 rows x 128B
            int idx = tid + i * 128;
            int row = idx >> 3, seg = idx & 7;
            uint32_t d = base + row * 128 +
                         ((uint32_t)((2 * seg) ^ ((row & 3) << 2)) << 3);
            CP_ASYNC16(d, Ag + (size_t)row * NN + k0 + seg * 8);
        }
#pragma unroll
        for (int i = 0; i < 4; i++) {        // B: 64 rows x 128B
            int idx = tid + i * 128;
            int row = idx >> 3, seg = idx & 7;
            uint32_t d = base + 16384 + row * 128 +
                         ((uint32_t)((2 * seg) ^ ((row & 3) << 2)) << 3);
            CP_ASYNC16(d, Bg + (size_t)row * NN + k0 + seg * 8);
        }
    };

    load_stage(0, 0);   CP_COMMIT();
    load_stage(1, 64);  CP_COMMIT();
    load_stage(2, 128); CP_COMMIT();

    const int r = lane >> 2, c = lane & 3;
    const int X = (r & 3) << 2;

    for (int kt = 0; kt < KT; kt++) {
        int s = kt & 3;
        asm volatile("cp.async.wait_group 2;" ::: "memory");
        __syncthreads();
        if (kt + 3 < KT) load_stage((kt + 3) & 3, (kt + 3) * 64);
        CP_COMMIT();

        const uint2* As2 = reinterpret_cast<const uint2*>(sm + (size_t)s * STG_F);
        const uint2* Bs2 = reinterpret_cast<const uint2*>(sm + (size_t)s * STG_F + 4096);
#pragma unroll
        for (int ks = 0; ks < 4; ks++) {      // 4 k-steps of K=16
            int sl = (4 * ks) ^ X;
            uint32_t a0[4], a1[4], a2[4], a3[4];
#pragma unroll
            for (int mt = 0; mt < 4; mt++) {
                int row0 = wm * 64 + mt * 16 + r;
                uint2 lo = As2[row0 * 16 + sl + c];
                uint2 hi = As2[(row0 + 8) * 16 + sl + c];
                a0[mt] = lo.x;
                a2[mt] = lo.y;
                a1[mt] = hi.x;
                a3[mt] = hi.y;
            }
#pragma unroll
            for (int nt = 0; nt < 4; nt++) {
                int nrow = wn * 32 + nt * 8 + r;
                uint2 bb = Bs2[nrow * 16 + sl + c];
#pragma unroll
                for (int mt = 0; mt < 4; mt++) {
                    asm volatile(
                        "mma.sync.aligned.m16n8k16.row.col.f32.f16.f16.f32 "
                        "{%0,%1,%2,%3}, {%4,%5,%6,%7}, {%8,%9}, {%0,%1,%2,%3};"
                        : "+f"(acc[mt][nt][0]), "+f"(acc[mt][nt][1]),
                          "+f"(acc[mt][nt][2]), "+f"(acc[mt][nt][3])
                        : "r"(a0[mt]), "r"(a1[mt]), "r"(a2[mt]), "r"(a3[mt]),
                          "r"(bb.x), "r"(bb.y));
                }
            }
        }
    }

#pragma unroll
    for (int mt = 0; mt < 4; mt++) {
        int row = m0 + wm * 64 + mt * 16 + r;
#pragma unroll
        for (int nt = 0; nt < 4; nt++) {
            int col = n0 + wn * 32 + nt * 8 + (c << 1);
            *reinterpret_cast<float2*>(&d_g2[(size_t)row * LDG2 + col]) =
                make_float2(acc[mt][nt][0], acc[mt][nt][1]);
            *reinterpret_cast<float2*>(&d_g2[(size_t)(row + 8) * LDG2 + col]) =
                make_float2(acc[mt][nt][2], acc[mt][nt][3]);
        }
    }
}

// ---------------- aggregate: one warp per segment, no atomics -----------------
__global__ void k_agg() {
    int warp = (blockIdx.x * blockDim.x + threadIdx.x) >> 5;
    int lane = threadIdx.x & 31;
    if (warp >= NSEG) return;
    int seg = warp;
    int t = seg % RR;
    int cnt = d_hcnt[seg];
    int base = d_base[seg];

    float4 acc = make_float4(0.f, 0.f, 0.f, 0.f);
    if (lane < 19) {
        for (int k = 0; k < cnt; k++) {
            int src = __ldg(&d_eidx[base + k]);
            const float4* grow = reinterpret_cast<const float4*>(
                d_g2 + (size_t)src * LDG2 + t * LDS2);
            float4 v = __ldg(grow + lane);
            acc.x += v.x; acc.y += v.y; acc.z += v.z; acc.w += v.w;
        }
        *reinterpret_cast<float4*>(d_sums + (size_t)seg * LDS2 + lane * 4) = acc;
    }
}

// ---------------- finalize: z -> BN(75) -> relu -> out -----------------------
__global__ void k_final(float* __restrict__ out,
                        const float* __restrict__ gu, const float* __restrict__ bu,
                        const float* __restrict__ gi, const float* __restrict__ bi) {
    int n = blockIdx.x;
    int tid = threadIdx.x;   // 128
    __shared__ float red[128];

    float zval = 0.f;
    if (tid < HH1) {
        float acc = d_biasV[tid] + d_g2[(size_t)n * LDG2 + RR * LDS2 + tid];
#pragma unroll
        for (int r = 0; r < RR; r++) {
            float c = d_cnt[n * RR + r];
            acc += d_sums[((size_t)(n * RR + r)) * LDS2 + tid] / fmaxf(c, 1.0f);
        }
        zval = acc;
    }
    red[tid] = zval;
    __syncthreads();
#pragma unroll
    for (int s = 64; s > 0; s >>= 1) {
        if (tid < s) red[tid] += red[tid + s];
        __syncthreads();
    }
    float mu = red[0] * (1.0f / HH1);
    __syncthreads();
    float d = (tid < HH1) ? (zval - mu) : 0.f;
    red[tid] = d * d;
    __syncthreads();
#pragma unroll
    for (int s = 64; s > 0; s >>= 1) {
        if (tid < s) red[tid] += red[tid + s];
        __syncthreads();
    }
    float var = red[0] * (1.0f / HH1);

    float gamma, beta;
    if (n < UU) { gamma = gu[n]; beta = bu[n]; }
    else        { gamma = gi[n - UU]; beta = bi[n - UU]; }

    if (tid < HH1) {
        float y = gamma * (zval - mu) * rsqrtf(var + 1e-5f) + beta;
        out[(size_t)n * HH1 + tid] = fmaxf(y, 0.f);
    }
}

// ---------------- launch ------------------------------------------------------
extern "C" void kernel_launch(void* const* d_in, const int* in_sizes, int n_in,
                              void* d_out, int out_size) {
    const float* x     = (const float*)d_in[0];
    const float* basis = (const float*)d_in[1];
    const float* comp  = (const float*)d_in[2];
    const float* root  = (const float*)d_in[3];
    const float* bias  = (const float*)d_in[4];
    const float* fc_w  = (const float*)d_in[5];
    const float* gu    = (const float*)d_in[6];
    const float* bu    = (const float*)d_in[7];
    const float* gi    = (const float*)d_in[8];
    const float* bi    = (const float*)d_in[9];
    const unsigned int* ei = (const unsigned int*)d_in[10];
    const unsigned int* et = (const unsigned int*)d_in[11];
    float* out = (float*)d_out;

    static int smem_set = 0;
    if (!smem_set) {
        cudaFuncSetAttribute(gemm2_mma, cudaFuncAttributeMaxDynamicSharedMemorySize,
                             4 * STG_F * 4);
        cudaFuncSetAttribute(gemmW, cudaFuncAttributeMaxDynamicSharedMemorySize,
                             4 * STGW_B);
        smem_set = 1;
    }

    // 1: fused prep (vectorized xp)
    k_prep<<<(NN * NN / 8) / 256, 256>>>(x, fc_w, bias, ei, et);
    // 2-3: start of edge chain
    k_hist<<<EE / 256, 256>>>(ei, et);
    k_scan1<<<160, 128>>>();
    // 4: buildW (float4 streaming)  <-- ncu capture slot
    k_buildW<<<(NN * 125 + 255) / 256, 256>>>(basis, root, comp);
    // rest of edge chain
    k_scan2<<<1, 256>>>();
    k_scan3<<<(NSEG + 255) / 256, 256>>>();
    k_scatter<<<EE / 256, 256>>>(ei, et);
    // small GEMM: VTp = (Wp @ fch^T)^T
    gemmW<<<dim3(1, 6 * NN / 128), 256, 4 * STGW_B>>>();
    // big GEMM
    gemm2_mma<<<dim3(8, 32), 128, 4 * STG_F * 4>>>();

    k_agg<<<NSEG / 8, 256>>>();
    k_final<<<NN, 128>>>(out, gu, bu, gi, bi);
}

// round 16
// speedup vs baseline: 1.0674x; 1.0674x over previous
#include <cuda_runtime.h>
#include <cuda_fp16.h>
#include <cstdint>

#define NN   4096
#define UU   2048
#define RR   5
#define BB   30
#define HH0  500
#define HH1  75
#define EE   262144
#define LDG2 512
#define LDS2 80           // padded d_sums / g2-block stride
#define KT   64           // GEMM2 k-tiles (K=4096, 64 halves per tile)
#define KPW  16           // gemmW k-tiles (K=512, 32 halves per tile)
#define NP   80           // gemmW N extent (75 padded to 80)
#define WSTR 80           // gemmW A/B smem row stride bytes (conflict-free LDS.32)
#define STGW_B (128 * WSTR + NP * WSTR)   // 16640 bytes per stage
#define NSEG (NN * RR)    // 20480 segments

// ---------------- scratch (device globals; no allocation allowed) ----------
__device__ __half d_fch[128 * 512];                 // fc_w fp16, natural order
__device__ __half d_xp[(size_t)NN * NN];            // x fp16 + k-permuted(16)
__device__ __half d_Wp[(size_t)6 * NN * 512];       // W fp16 [6*4096][512] (blk5=root)
__device__ __half d_VTp[(size_t)LDG2 * NN];         // V^T fp16+perm; row 80r+j; pad 0
__device__ float  d_g2[(size_t)NN * LDG2];          // g[n][80r+j]
__device__ float  d_sums[(size_t)NSEG * LDS2];
__device__ float  d_cnt[NSEG];
__device__ float  d_biasV[HH1];
__device__ int    d_i64flag[2];
// edge sort scratch
__device__ int d_hcnt[NSEG];
__device__ int d_bsum[160];
__device__ int d_bbase[160];
__device__ int d_base[NSEG];
__device__ int d_wptr[NSEG];
__device__ int d_eidx[EE];

// ---------------- small helpers --------------------------------------------
__device__ __forceinline__ uint32_t smem_u32(const void* p) {
    uint32_t a;
    asm("{ .reg .u64 t; cvta.to.shared.u64 t, %1; cvt.u32.u64 %0, t; }"
        : "=r"(a) : "l"(p));
    return a;
}
__device__ __forceinline__ uint32_t packh2(float a, float b) {
    __half2 h = __floats2half2_rn(a, b);
    return *reinterpret_cast<uint32_t*>(&h);
}
#define CP_ASYNC16(dst, src) \
    asm volatile("cp.async.cg.shared.global [%0], [%1], 16;" :: "r"(dst), "l"(src))
#define CP_COMMIT() asm volatile("cp.async.commit_group;" ::: "memory")

__device__ __forceinline__ void edge_seg(const unsigned int* ei,
                                         const unsigned int* et, int e,
                                         int& src, int& seg) {
    long long s, d, t;
    if (d_i64flag[0]) {
        s = reinterpret_cast<const long long*>(ei)[e];
        d = reinterpret_cast<const long long*>(ei)[EE + e];
    } else {
        s = reinterpret_cast<const int*>(ei)[e];
        d = reinterpret_cast<const int*>(ei)[EE + e];
    }
    t = d_i64flag[1] ? reinterpret_cast<const long long*>(et)[e]
                     : (long long)reinterpret_cast<const int*>(et)[e];
    src = (int)s;
    seg = (int)d * RR + (int)t;
}

// ---------------- fused prep: xp(half2, R14-proven) + detect + fch + biasV ---
__global__ void k_prep(const float* __restrict__ x,
                       const float* __restrict__ fc_w,
                       const float* __restrict__ bias,
                       const unsigned int* __restrict__ ei,
                       const unsigned int* __restrict__ et) {
    int idx = blockIdx.x * blockDim.x + threadIdx.x;   // over NN*NN/2

    {   // xp: fp16 convert + 16-perm; each thread writes one half2
        int row = idx >> 11;
        int hp = (idx & 2047) << 1;        // even stored position
        int p = hp & 15;                    // even: w = 0
        int s = p >> 2, h = (p >> 1) & 1;
        int sk = (hp & ~15) + s * 2 + h * 8;
        const float* xr = x + (size_t)row * NN;
        reinterpret_cast<__half2*>(d_xp)[idx] =
            __halves2half2(__float2half_rn(xr[sk]), __float2half_rn(xr[sk + 1]));
    }
    if (idx < 128 * 512) {                 // fch: fp16, natural order, zero pad
        int n = idx >> 9, k = idx & 511;
        float v = (n < HH1 && k < HH0) ? fc_w[n * HH0 + k] : 0.f;
        d_fch[idx] = __float2half_rn(v);
    }
    if (idx < NSEG) d_hcnt[idx] = 0;
    if (idx < HH1) {                       // biasV
        float s = 0.f;
        const float* fw = fc_w + idx * HH0;
        for (int o = 0; o < HH0; o++) s = fmaf(bias[o], fw[o], s);
        d_biasV[idx] = s;
    }
    if (blockIdx.x == 0 && threadIdx.x < 64) {
        int w = threadIdx.x >> 5, lane = threadIdx.x & 31;
        unsigned v = (w == 0) ? ei[2 * lane + 1] : et[2 * lane + 1];
        unsigned b = __ballot_sync(0xFFFFFFFFu, v != 0u);
        if (lane == 0) d_i64flag[w] = (b == 0u);
    }
}

// ---------------- buildW (float4): Wp = fp16(comp x basis), + root, + pad ----
__global__ void k_buildW(const float* __restrict__ basis,
                         const float* __restrict__ root,
                         const float* __restrict__ comp) {
    __shared__ float sc[RR * BB];
    if (threadIdx.x < RR * BB) sc[threadIdx.x] = comp[threadIdx.x];
    __syncthreads();
    int idx = blockIdx.x * blockDim.x + threadIdx.x;   // over NN*125
    if (idx >= NN * 125) return;
    int i = idx / 125, o4 = idx - i * 125;             // o = o4*4
    size_t src_off = (size_t)i * HH0 + o4 * 4;

    float4 acc[RR];
#pragma unroll
    for (int r = 0; r < RR; r++) acc[r] = make_float4(0.f, 0.f, 0.f, 0.f);
#pragma unroll 5
    for (int b = 0; b < BB; b++) {
        float4 v = *reinterpret_cast<const float4*>(
            basis + (size_t)b * (NN * HH0) + src_off);
#pragma unroll
        for (int r = 0; r < RR; r++) {
            float cc = sc[r * BB + b];
            acc[r].x = fmaf(cc, v.x, acc[r].x);
            acc[r].y = fmaf(cc, v.y, acc[r].y);
            acc[r].z = fmaf(cc, v.z, acc[r].z);
            acc[r].w = fmaf(cc, v.w, acc[r].w);
        }
    }
#pragma unroll
    for (int r = 0; r < RR; r++) {
        uint2 o;
        o.x = packh2(acc[r].x, acc[r].y);
        o.y = packh2(acc[r].z, acc[r].w);
        *reinterpret_cast<uint2*>(d_Wp + (((size_t)(r * NN + i)) << 9) + o4 * 4) = o;
    }
    {
        float4 rv = *reinterpret_cast<const float4*>(root + src_off);
        uint2 o;
        o.x = packh2(rv.x, rv.y);
        o.y = packh2(rv.z, rv.w);
        *reinterpret_cast<uint2*>(d_Wp + (((size_t)(RR * NN + i)) << 9) + o4 * 4) = o;
    }
    // zero-pad o = 500..511 for all 6*NN rows: 3 x uint2 (4 halves) per row
    if (idx < 6 * NN * 3) {
        int row = idx / 3, q = idx - row * 3;
        uint2 z = make_uint2(0u, 0u);
        *reinterpret_cast<uint2*>(d_Wp + ((size_t)row << 9) + 500 + q * 4) = z;
    }
}

// ---------------- edge sort: histogram ---------------------------------------
__global__ void k_hist(const unsigned int* __restrict__ ei,
                       const unsigned int* __restrict__ et) {
    int e = blockIdx.x * blockDim.x + threadIdx.x;
    if (e >= EE) return;
    int src, seg;
    edge_seg(ei, et, e, src, seg);
    atomicAdd(&d_hcnt[seg], 1);
}

// ---------------- scan stage 1 ------------------------------------------------
__global__ void k_scan1() {
    int tid = threadIdx.x;
    int i = blockIdx.x * 128 + tid;
    int lane = tid & 31, w = tid >> 5;
    int v = d_hcnt[i];
    int x = v;
#pragma unroll
    for (int o = 1; o < 32; o <<= 1) {
        int y = __shfl_up_sync(0xFFFFFFFFu, x, o);
        if (lane >= o) x += y;
    }
    __shared__ int ws[4], we[4];
    if (lane == 31) ws[w] = x;
    __syncthreads();
    if (tid == 0) {
        int run = 0;
        for (int k = 0; k < 4; k++) { we[k] = run; run += ws[k]; }
        d_bsum[blockIdx.x] = run;
    }
    __syncthreads();
    d_base[i] = (x - v) + we[w];
}

// ---------------- scan stage 2 ------------------------------------------------
__global__ void k_scan2() {
    int tid = threadIdx.x;   // 256
    int lane = tid & 31, w = tid >> 5;
    int v = (tid < 160) ? d_bsum[tid] : 0;
    int x = v;
#pragma unroll
    for (int o = 1; o < 32; o <<= 1) {
        int y = __shfl_up_sync(0xFFFFFFFFu, x, o);
        if (lane >= o) x += y;
    }
    __shared__ int ws[8], we[8];
    if (lane == 31) ws[w] = x;
    __syncthreads();
    if (tid == 0) {
        int run = 0;
        for (int k = 0; k < 8; k++) { we[k] = run; run += ws[k]; }
    }
    __syncthreads();
    if (tid < 160) d_bbase[tid] = (x - v) + we[w];
}

// ---------------- scan stage 3 ------------------------------------------------
__global__ void k_scan3() {
    int i = blockIdx.x * blockDim.x + threadIdx.x;
    if (i >= NSEG) return;
    int b = d_base[i] + d_bbase[i >> 7];
    d_base[i] = b;
    d_wptr[i] = b;
    d_cnt[i] = (float)d_hcnt[i];
}

// ---------------- scatter: CSR fill ------------------------------------------
__global__ void k_scatter(const unsigned int* __restrict__ ei,
                          const unsigned int* __restrict__ et) {
    int e = blockIdx.x * blockDim.x + threadIdx.x;
    if (e >= EE) return;
    int src, seg;
    edge_seg(ei, et, e, src, seg);
    int pos = atomicAdd(&d_wptr[seg], 1);
    d_eidx[pos] = src;
}

// ---------------- gemmW (TC fp16): VTp = (Wp @ fch^T)^T, M=24576, N=80 -------
__global__ void __launch_bounds__(256, 2) gemmW() {
    extern __shared__ char smc[];
    uint32_t smb = smem_u32(smc);
    int tid = threadIdx.x;
    int lane = tid & 31, wid = tid >> 5;
    int wm = wid & 3, wn = wid >> 2;     // 4 x 2 warps: 32(M) x 40(N)
    int m0 = blockIdx.y * 128;
    const __half* Ag = d_Wp + ((size_t)m0 << 9);

    float acc[2][5][4];
#pragma unroll
    for (int a = 0; a < 2; a++)
#pragma unroll
        for (int b = 0; b < 5; b++)
#pragma unroll
            for (int d = 0; d < 4; d++) acc[a][b][d] = 0.f;

    auto load_stage = [&](int s, int k0) {   // k0 in halves (32 per tile)
        uint32_t base = smb + (uint32_t)s * STGW_B;
#pragma unroll
        for (int i = 0; i < 2; i++) {        // A: 128 rows x 4 chunks of 16B
            int idx = tid + i * 256;
            int row = idx >> 2, m = idx & 3;
            CP_ASYNC16(base + row * WSTR + m * 16,
                       Ag + ((size_t)row << 9) + k0 + m * 8);
        }
#pragma unroll
        for (int i = 0; i < 2; i++) {        // B: 80 rows x 4 chunks of 16B
            int idx = tid + i * 256;
            if (idx < NP * 4) {
                int row = idx >> 2, m = idx & 3;
                CP_ASYNC16(base + 128 * WSTR + row * WSTR + m * 16,
                           d_fch + ((size_t)row << 9) + k0 + m * 8);
            }
        }
    };

    load_stage(0, 0);  CP_COMMIT();
    load_stage(1, 32); CP_COMMIT();
    load_stage(2, 64); CP_COMMIT();

    const int r = lane >> 2, c = lane & 3;

    for (int kt = 0; kt < KPW; kt++) {
        int s = kt & 3;
        asm volatile("cp.async.wait_group 2;" ::: "memory");
        __syncthreads();
        if (kt + 3 < KPW) load_stage((kt + 3) & 3, (kt + 3) * 32);
        CP_COMMIT();

        const char* Asf = smc + (size_t)s * STGW_B;
        const char* Bsf = Asf + 128 * WSTR;
#pragma unroll
        for (int kk = 0; kk < 2; kk++) {      // 2 k-steps of K=16
            uint32_t a0[2], a1[2], a2[2], a3[2];
#pragma unroll
            for (int mt = 0; mt < 2; mt++) {
                int ro = wm * 32 + mt * 16 + r;
                a0[mt] = *reinterpret_cast<const uint32_t*>(Asf + ro * WSTR + (8 * kk + c) * 4);
                a2[mt] = *reinterpret_cast<const uint32_t*>(Asf + ro * WSTR + (8 * kk + 4 + c) * 4);
                a1[mt] = *reinterpret_cast<const uint32_t*>(Asf + (ro + 8) * WSTR + (8 * kk + c) * 4);
                a3[mt] = *reinterpret_cast<const uint32_t*>(Asf + (ro + 8) * WSTR + (8 * kk + 4 + c) * 4);
            }
#pragma unroll
            for (int nt = 0; nt < 5; nt++) {
                int n = wn * 40 + nt * 8 + r;
                uint32_t b0 = *reinterpret_cast<const uint32_t*>(
                    Bsf + n * WSTR + (8 * kk + c) * 4);
                uint32_t b1 = *reinterpret_cast<const uint32_t*>(
                    Bsf + n * WSTR + (8 * kk + 4 + c) * 4);
#pragma unroll
                for (int mt = 0; mt < 2; mt++) {
                    asm volatile(
                        "mma.sync.aligned.m16n8k16.row.col.f32.f16.f16.f32 "
                        "{%0,%1,%2,%3}, {%4,%5,%6,%7}, {%8,%9}, {%0,%1,%2,%3};"
                        : "+f"(acc[mt][nt][0]), "+f"(acc[mt][nt][1]),
                          "+f"(acc[mt][nt][2]), "+f"(acc[mt][nt][3])
                        : "r"(a0[mt]), "r"(a1[mt]), "r"(a2[mt]), "r"(a3[mt]),
                          "r"(b0), "r"(b1));
                }
            }
        }
    }

    // epilogue: VTp[(80*r5 + col)][perm16(i)] = fp16(acc)
#pragma unroll
    for (int mt = 0; mt < 2; mt++) {
        int m = m0 + wm * 32 + mt * 16 + r;
        int r5 = m >> 12;
        int i1 = m & 4095;
        int i2 = i1 + 8;
        int k1 = i1 & 15, k2 = i2 & 15;
        int pos1 = (i1 & ~15) | ((((k1 & 7) >> 1) << 2) | ((k1 >> 3) << 1) | (k1 & 1));
        int pos2 = (i2 & ~15) | ((((k2 & 7) >> 1) << 2) | ((k2 >> 3) << 1) | (k2 & 1));
#pragma unroll
        for (int nt = 0; nt < 5; nt++) {
            int col = wn * 40 + nt * 8 + 2 * c;
            if (col < HH1) {
                size_t vr = (size_t)(r5 * LDS2 + col) << 12;
                d_VTp[vr + pos1] = __float2half_rn(acc[mt][nt][0]);
                d_VTp[vr + pos2] = __float2half_rn(acc[mt][nt][2]);
            }
            if (col + 1 < HH1) {
                size_t vr = (size_t)(r5 * LDS2 + col + 1) << 12;
                d_VTp[vr + pos1] = __float2half_rn(acc[mt][nt][1]);
                d_VTp[vr + pos2] = __float2half_rn(acc[mt][nt][3]);
            }
        }
    }
}

// ---------------- GEMM2 (TC fp16 m16n8k16): g2 = xp @ VTp^T ------------------
#define STG_F 6144   // floats per stage: A 16KB + B 8KB

__global__ void __launch_bounds__(128, 2) gemm2_mma() {
    extern __shared__ float sm[];
    uint32_t smb = smem_u32(sm);
    int tid = threadIdx.x;             // 128 threads
    int lane = tid & 31, wid = tid >> 5;
    int wm = wid & 1, wn = wid >> 1;   // 4 warps: 2(M) x 2(N), 64x32 each
    int m0 = blockIdx.y * 128, n0 = blockIdx.x * 64;
    const __half* Ag = d_xp + (size_t)m0 * NN;
    const __half* Bg = d_VTp + (size_t)n0 * NN;

    float acc[4][4][4];
#pragma unroll
    for (int a = 0; a < 4; a++)
#pragma unroll
        for (int b = 0; b < 4; b++)
#pragma unroll
            for (int d = 0; d < 4; d++) acc[a][b][d] = 0.f;

    auto load_stage = [&](int s, int k0) {   // k0 in halves
        uint32_t base = smb + (uint32_t)s * (STG_F * 4);
#pragma unroll
        for (int i = 0; i < 8; i++) {        // A: 128 rows x 128B
            int idx = tid + i * 128;
            int row = idx >> 3, seg = idx & 7;
            uint32_t d = base + row * 128 +
                         ((uint32_t)((2 * seg) ^ ((row & 3) << 2)) << 3);
            CP_ASYNC16(d, Ag + (size_t)row * NN + k0 + seg * 8);
        }
#pragma unroll
        for (int i = 0; i < 4; i++) {        // B: 64 rows x 128B
            int idx = tid + i * 128;
            int row = idx >> 3, seg = idx & 7;
            uint32_t d = base + 16384 + row * 128 +
                         ((uint32_t)((2 * seg) ^ ((row & 3) << 2)) << 3);
            CP_ASYNC16(d, Bg + (size_t)row * NN + k0 + seg * 8);
        }
    };

    load_stage(0, 0);   CP_COMMIT();
    load_stage(1, 64);  CP_COMMIT();
    load_stage(2, 128); CP_COMMIT();

    const int r = lane >> 2, c = lane & 3;
    const int X = (r & 3) << 2;

    for (int kt = 0; kt < KT; kt++) {
        int s = kt & 3;
        asm volatile("cp.async.wait_group 2;" ::: "memory");
        __syncthreads();
        if (kt + 3 < KT) load_stage((kt + 3) & 3, (kt + 3) * 64);
        CP_COMMIT();

        const uint2* As2 = reinterpret_cast<const uint2*>(sm + (size_t)s * STG_F);
        const uint2* Bs2 = reinterpret_cast<const uint2*>(sm + (size_t)s * STG_F + 4096);
#pragma unroll
        for (int ks = 0; ks < 4; ks++) {      // 4 k-steps of K=16
            int sl = (4 * ks) ^ X;
            uint32_t a0[4], a1[4], a2[4], a3[4];
#pragma unroll
            for (int mt = 0; mt < 4; mt++) {
                int row0 = wm * 64 + mt * 16 + r;
                uint2 lo = As2[row0 * 16 + sl + c];
                uint2 hi = As2[(row0 + 8) * 16 + sl + c];
                a0[mt] = lo.x;
                a2[mt] = lo.y;
                a1[mt] = hi.x;
                a3[mt] = hi.y;
            }
#pragma unroll
            for (int nt = 0; nt < 4; nt++) {
                int nrow = wn * 32 + nt * 8 + r;
                uint2 bb = Bs2[nrow * 16 + sl + c];
#pragma unroll
                for (int mt = 0; mt < 4; mt++) {
                    asm volatile(
                        "mma.sync.aligned.m16n8k16.row.col.f32.f16.f16.f32 "
                        "{%0,%1,%2,%3}, {%4,%5,%6,%7}, {%8,%9}, {%0,%1,%2,%3};"
                        : "+f"(acc[mt][nt][0]), "+f"(acc[mt][nt][1]),
                          "+f"(acc[mt][nt][2]), "+f"(acc[mt][nt][3])
                        : "r"(a0[mt]), "r"(a1[mt]), "r"(a2[mt]), "r"(a3[mt]),
                          "r"(bb.x), "r"(bb.y));
                }
            }
        }
    }

#pragma unroll
    for (int mt = 0; mt < 4; mt++) {
        int row = m0 + wm * 64 + mt * 16 + r;
#pragma unroll
        for (int nt = 0; nt < 4; nt++) {
            int col = n0 + wn * 32 + nt * 8 + (c << 1);
            *reinterpret_cast<float2*>(&d_g2[(size_t)row * LDG2 + col]) =
                make_float2(acc[mt][nt][0], acc[mt][nt][1]);
            *reinterpret_cast<float2*>(&d_g2[(size_t)(row + 8) * LDG2 + col]) =
                make_float2(acc[mt][nt][2], acc[mt][nt][3]);
        }
    }
}

// ---------------- aggregate: one warp per segment, no atomics -----------------
__global__ void k_agg() {
    int warp = (blockIdx.x * blockDim.x + threadIdx.x) >> 5;
    int lane = threadIdx.x & 31;
    if (warp >= NSEG) return;
    int seg = warp;
    int t = seg % RR;
    int cnt = d_hcnt[seg];
    int base = d_base[seg];

    float4 acc = make_float4(0.f, 0.f, 0.f, 0.f);
    if (lane < 19) {
        for (int k = 0; k < cnt; k++) {
            int src = __ldg(&d_eidx[base + k]);
            const float4* grow = reinterpret_cast<const float4*>(
                d_g2 + (size_t)src * LDG2 + t * LDS2);
            float4 v = __ldg(grow + lane);
            acc.x += v.x; acc.y += v.y; acc.z += v.z; acc.w += v.w;
        }
        *reinterpret_cast<float4*>(d_sums + (size_t)seg * LDS2 + lane * 4) = acc;
    }
}

// ---------------- finalize: z -> BN(75) -> relu -> out -----------------------
__global__ void k_final(float* __restrict__ out,
                        const float* __restrict__ gu, const float* __restrict__ bu,
                        const float* __restrict__ gi, const float* __restrict__ bi) {
    int n = blockIdx.x;
    int tid = threadIdx.x;   // 128
    __shared__ float red[128];

    float zval = 0.f;
    if (tid < HH1) {
        float acc = d_biasV[tid] + d_g2[(size_t)n * LDG2 + RR * LDS2 + tid];
#pragma unroll
        for (int r = 0; r < RR; r++) {
            float c = d_cnt[n * RR + r];
            acc += d_sums[((size_t)(n * RR + r)) * LDS2 + tid] / fmaxf(c, 1.0f);
        }
        zval = acc;
    }
    red[tid] = zval;
    __syncthreads();
#pragma unroll
    for (int s = 64; s > 0; s >>= 1) {
        if (tid < s) red[tid] += red[tid + s];
        __syncthreads();
    }
    float mu = red[0] * (1.0f / HH1);
    __syncthreads();
    float d = (tid < HH1) ? (zval - mu) : 0.f;
    red[tid] = d * d;
    __syncthreads();
#pragma unroll
    for (int s = 64; s > 0; s >>= 1) {
        if (tid < s) red[tid] += red[tid + s];
        __syncthreads();
    }
    float var = red[0] * (1.0f / HH1);

    float gamma, beta;
    if (n < UU) { gamma = gu[n]; beta = bu[n]; }
    else        { gamma = gi[n - UU]; beta = bi[n - UU]; }

    if (tid < HH1) {
        float y = gamma * (zval - mu) * rsqrtf(var + 1e-5f) + beta;
        out[(size_t)n * HH1 + tid] = fmaxf(y, 0.f);
    }
}

// ---------------- launch ------------------------------------------------------
extern "C" void kernel_launch(void* const* d_in, const int* in_sizes, int n_in,
                              void* d_out, int out_size) {
    const float* x     = (const float*)d_in[0];
    const float* basis = (const float*)d_in[1];
    const float* comp  = (const float*)d_in[2];
    const float* root  = (const float*)d_in[3];
    const float* bias  = (const float*)d_in[4];
    const float* fc_w  = (const float*)d_in[5];
    const float* gu    = (const float*)d_in[6];
    const float* bu    = (const float*)d_in[7];
    const float* gi    = (const float*)d_in[8];
    const float* bi    = (const float*)d_in[9];
    const unsigned int* ei = (const unsigned int*)d_in[10];
    const unsigned int* et = (const unsigned int*)d_in[11];
    float* out = (float*)d_out;

    static int smem_set = 0;
    if (!smem_set) {
        cudaFuncSetAttribute(gemm2_mma, cudaFuncAttributeMaxDynamicSharedMemorySize,
                             4 * STG_F * 4);
        cudaFuncSetAttribute(gemmW, cudaFuncAttributeMaxDynamicSharedMemorySize,
                             4 * STGW_B);
        smem_set = 1;
    }

    // 1: fused prep (half2 xp — R14-proven)
    k_prep<<<(NN * NN / 2) / 256, 256>>>(x, fc_w, bias, ei, et);
    // 2-3: start of edge chain
    k_hist<<<EE / 256, 256>>>(ei, et);
    k_scan1<<<160, 128>>>();
    // 4: buildW (float4 streaming)  <-- ncu capture slot
    k_buildW<<<(NN * 125 + 255) / 256, 256>>>(basis, root, comp);
    // rest of edge chain
    k_scan2<<<1, 256>>>();
    k_scan3<<<(NSEG + 255) / 256, 256>>>();
    k_scatter<<<EE / 256, 256>>>(ei, et);
    // small GEMM: VTp = (Wp @ fch^T)^T
    gemmW<<<dim3(1, 6 * NN / 128), 256, 4 * STGW_B>>>();
    // big GEMM
    gemm2_mma<<<dim3(8, 32), 128, 4 * STG_F * 4>>>();

    k_agg<<<NSEG / 8, 256>>>();
    k_final<<<NN, 128>>>(out, gu, bu, gi, bi);
}

// round 17
// speedup vs baseline: 1.1152x; 1.0448x over previous
#include <cuda_runtime.h>
#include <cuda_fp16.h>
#include <cstdint>

#define NN   4096
#define UU   2048
#define RR   5
#define BB   30
#define HH0  500
#define HH1  75
#define EE   262144
#define LDG2 512
#define LDS2 80           // padded d_sums / g2-block stride
#define KT   64           // GEMM2 k-tiles (K=4096, 64 halves per tile)
#define KPW  16           // gemmW k-tiles (K=512, 32 halves per tile)
#define NP   80           // gemmW N extent (75 padded to 80)
#define WSTR 80           // gemmW A/B smem row stride bytes (conflict-free LDS.32)
#define STGW_B (128 * WSTR + NP * WSTR)   // 16640 bytes per stage
#define NSEG (NN * RR)    // 20480 segments

// ---------------- scratch (device globals; no allocation allowed) ----------
__device__ __half d_fch[128 * 512];                 // fc_w fp16, natural order
__device__ __half d_xp[(size_t)NN * NN];            // x fp16 + k-permuted(16)
__device__ __half d_Wp[(size_t)6 * NN * 512];       // W fp16 [6*4096][512] (blk5=root)
__device__ __half d_VTp[(size_t)LDG2 * NN];         // V^T fp16+perm; row 80r+j; pad 0
__device__ float  d_g2[(size_t)NN * LDG2];          // g[n][80r+j]
__device__ float  d_sums[(size_t)NSEG * LDS2];
__device__ float  d_cnt[NSEG];
__device__ float  d_biasV[HH1];
__device__ int    d_i64flag[2];
// edge sort scratch
__device__ int d_hcnt[NSEG];
__device__ int d_bsum[160];
__device__ int d_bbase[160];
__device__ int d_base[NSEG];
__device__ int d_wptr[NSEG];
__device__ int d_eidx[EE];

// ---------------- small helpers --------------------------------------------
__device__ __forceinline__ uint32_t smem_u32(const void* p) {
    uint32_t a;
    asm("{ .reg .u64 t; cvta.to.shared.u64 t, %1; cvt.u32.u64 %0, t; }"
        : "=r"(a) : "l"(p));
    return a;
}
__device__ __forceinline__ uint32_t packh2(float a, float b) {
    __half2 h = __floats2half2_rn(a, b);
    return *reinterpret_cast<uint32_t*>(&h);
}
#define CP_ASYNC16(dst, src) \
    asm volatile("cp.async.cg.shared.global [%0], [%1], 16;" :: "r"(dst), "l"(src))
#define CP_COMMIT() asm volatile("cp.async.commit_group;" ::: "memory")

__device__ __forceinline__ void edge_seg(const unsigned int* ei,
                                         const unsigned int* et, int e,
                                         int& src, int& seg) {
    long long s, d, t;
    if (d_i64flag[0]) {
        s = reinterpret_cast<const long long*>(ei)[e];
        d = reinterpret_cast<const long long*>(ei)[EE + e];
    } else {
        s = reinterpret_cast<const int*>(ei)[e];
        d = reinterpret_cast<const int*>(ei)[EE + e];
    }
    t = d_i64flag[1] ? reinterpret_cast<const long long*>(et)[e]
                     : (long long)reinterpret_cast<const int*>(et)[e];
    src = (int)s;
    seg = (int)d * RR + (int)t;
}

// ---------------- detect: dtype flags + zero d_hcnt (runs before fork) -------
__global__ void k_detect(const unsigned int* __restrict__ ei,
                         const unsigned int* __restrict__ et) {
    int idx = blockIdx.x * blockDim.x + threadIdx.x;   // grid 80*256 = 20480
    if (idx < NSEG) d_hcnt[idx] = 0;
    if (blockIdx.x == 0 && threadIdx.x < 64) {
        int w = threadIdx.x >> 5, lane = threadIdx.x & 31;
        unsigned v = (w == 0) ? ei[2 * lane + 1] : et[2 * lane + 1];
        unsigned b = __ballot_sync(0xFFFFFFFFu, v != 0u);
        if (lane == 0) d_i64flag[w] = (b == 0u);
    }
}

// ---------------- fused prep: xp(half2) + fch + biasV ------------------------
__global__ void k_prep(const float* __restrict__ x,
                       const float* __restrict__ fc_w,
                       const float* __restrict__ bias) {
    int idx = blockIdx.x * blockDim.x + threadIdx.x;   // over NN*NN/2

    {   // xp: fp16 convert + 16-perm; each thread writes one half2
        int row = idx >> 11;
        int hp = (idx & 2047) << 1;        // even stored position
        int p = hp & 15;                    // even: w = 0
        int s = p >> 2, h = (p >> 1) & 1;
        int sk = (hp & ~15) + s * 2 + h * 8;
        const float* xr = x + (size_t)row * NN;
        reinterpret_cast<__half2*>(d_xp)[idx] =
            __halves2half2(__float2half_rn(xr[sk]), __float2half_rn(xr[sk + 1]));
    }
    if (idx < 128 * 512) {                 // fch: fp16, natural order, zero pad
        int n = idx >> 9, k = idx & 511;
        float v = (n < HH1 && k < HH0) ? fc_w[n * HH0 + k] : 0.f;
        d_fch[idx] = __float2half_rn(v);
    }
    if (idx < HH1) {                       // biasV
        float s = 0.f;
        const float* fw = fc_w + idx * HH0;
        for (int o = 0; o < HH0; o++) s = fmaf(bias[o], fw[o], s);
        d_biasV[idx] = s;
    }
}

// ---------------- buildW (float4): Wp = fp16(comp x basis), + root, + pad ----
__global__ void k_buildW(const float* __restrict__ basis,
                         const float* __restrict__ root,
                         const float* __restrict__ comp) {
    __shared__ float sc[RR * BB];
    if (threadIdx.x < RR * BB) sc[threadIdx.x] = comp[threadIdx.x];
    __syncthreads();
    int idx = blockIdx.x * blockDim.x + threadIdx.x;   // over NN*125
    if (idx >= NN * 125) return;
    int i = idx / 125, o4 = idx - i * 125;             // o = o4*4
    size_t src_off = (size_t)i * HH0 + o4 * 4;

    float4 acc[RR];
#pragma unroll
    for (int r = 0; r < RR; r++) acc[r] = make_float4(0.f, 0.f, 0.f, 0.f);
#pragma unroll 5
    for (int b = 0; b < BB; b++) {
        float4 v = *reinterpret_cast<const float4*>(
            basis + (size_t)b * (NN * HH0) + src_off);
#pragma unroll
        for (int r = 0; r < RR; r++) {
            float cc = sc[r * BB + b];
            acc[r].x = fmaf(cc, v.x, acc[r].x);
            acc[r].y = fmaf(cc, v.y, acc[r].y);
            acc[r].z = fmaf(cc, v.z, acc[r].z);
            acc[r].w = fmaf(cc, v.w, acc[r].w);
        }
    }
#pragma unroll
    for (int r = 0; r < RR; r++) {
        uint2 o;
        o.x = packh2(acc[r].x, acc[r].y);
        o.y = packh2(acc[r].z, acc[r].w);
        *reinterpret_cast<uint2*>(d_Wp + (((size_t)(r * NN + i)) << 9) + o4 * 4) = o;
    }
    {
        float4 rv = *reinterpret_cast<const float4*>(root + src_off);
        uint2 o;
        o.x = packh2(rv.x, rv.y);
        o.y = packh2(rv.z, rv.w);
        *reinterpret_cast<uint2*>(d_Wp + (((size_t)(RR * NN + i)) << 9) + o4 * 4) = o;
    }
    // zero-pad o = 500..511 for all 6*NN rows: 3 x uint2 (4 halves) per row
    if (idx < 6 * NN * 3) {
        int row = idx / 3, q = idx - row * 3;
        uint2 z = make_uint2(0u, 0u);
        *reinterpret_cast<uint2*>(d_Wp + ((size_t)row << 9) + 500 + q * 4) = z;
    }
}

// ---------------- edge sort: histogram ---------------------------------------
__global__ void k_hist(const unsigned int* __restrict__ ei,
                       const unsigned int* __restrict__ et) {
    int e = blockIdx.x * blockDim.x + threadIdx.x;
    if (e >= EE) return;
    int src, seg;
    edge_seg(ei, et, e, src, seg);
    atomicAdd(&d_hcnt[seg], 1);
}

// ---------------- scan stage 1 ------------------------------------------------
__global__ void k_scan1() {
    int tid = threadIdx.x;
    int i = blockIdx.x * 128 + tid;
    int lane = tid & 31, w = tid >> 5;
    int v = d_hcnt[i];
    int x = v;
#pragma unroll
    for (int o = 1; o < 32; o <<= 1) {
        int y = __shfl_up_sync(0xFFFFFFFFu, x, o);
        if (lane >= o) x += y;
    }
    __shared__ int ws[4], we[4];
    if (lane == 31) ws[w] = x;
    __syncthreads();
    if (tid == 0) {
        int run = 0;
        for (int k = 0; k < 4; k++) { we[k] = run; run += ws[k]; }
        d_bsum[blockIdx.x] = run;
    }
    __syncthreads();
    d_base[i] = (x - v) + we[w];
}

// ---------------- scan stage 2 ------------------------------------------------
__global__ void k_scan2() {
    int tid = threadIdx.x;   // 256
    int lane = tid & 31, w = tid >> 5;
    int v = (tid < 160) ? d_bsum[tid] : 0;
    int x = v;
#pragma unroll
    for (int o = 1; o < 32; o <<= 1) {
        int y = __shfl_up_sync(0xFFFFFFFFu, x, o);
        if (lane >= o) x += y;
    }
    __shared__ int ws[8], we[8];
    if (lane == 31) ws[w] = x;
    __syncthreads();
    if (tid == 0) {
        int run = 0;
        for (int k = 0; k < 8; k++) { we[k] = run; run += ws[k]; }
    }
    __syncthreads();
    if (tid < 160) d_bbase[tid] = (x - v) + we[w];
}

// ---------------- scan stage 3 ------------------------------------------------
__global__ void k_scan3() {
    int i = blockIdx.x * blockDim.x + threadIdx.x;
    if (i >= NSEG) return;
    int b = d_base[i] + d_bbase[i >> 7];
    d_base[i] = b;
    d_wptr[i] = b;
    d_cnt[i] = (float)d_hcnt[i];
}

// ---------------- scatter: CSR fill ------------------------------------------
__global__ void k_scatter(const unsigned int* __restrict__ ei,
                          const unsigned int* __restrict__ et) {
    int e = blockIdx.x * blockDim.x + threadIdx.x;
    if (e >= EE) return;
    int src, seg;
    edge_seg(ei, et, e, src, seg);
    int pos = atomicAdd(&d_wptr[seg], 1);
    d_eidx[pos] = src;
}

// ---------------- gemmW (TC fp16): VTp = (Wp @ fch^T)^T, M=24576, N=80 -------
__global__ void __launch_bounds__(256, 2) gemmW() {
    extern __shared__ char smc[];
    uint32_t smb = smem_u32(smc);
    int tid = threadIdx.x;
    int lane = tid & 31, wid = tid >> 5;
    int wm = wid & 3, wn = wid >> 2;     // 4 x 2 warps: 32(M) x 40(N)
    int m0 = blockIdx.y * 128;
    const __half* Ag = d_Wp + ((size_t)m0 << 9);

    float acc[2][5][4];
#pragma unroll
    for (int a = 0; a < 2; a++)
#pragma unroll
        for (int b = 0; b < 5; b++)
#pragma unroll
            for (int d = 0; d < 4; d++) acc[a][b][d] = 0.f;

    auto load_stage = [&](int s, int k0) {   // k0 in halves (32 per tile)
        uint32_t base = smb + (uint32_t)s * STGW_B;
#pragma unroll
        for (int i = 0; i < 2; i++) {        // A: 128 rows x 4 chunks of 16B
            int idx = tid + i * 256;
            int row = idx >> 2, m = idx & 3;
            CP_ASYNC16(base + row * WSTR + m * 16,
                       Ag + ((size_t)row << 9) + k0 + m * 8);
        }
#pragma unroll
        for (int i = 0; i < 2; i++) {        // B: 80 rows x 4 chunks of 16B
            int idx = tid + i * 256;
            if (idx < NP * 4) {
                int row = idx >> 2, m = idx & 3;
                CP_ASYNC16(base + 128 * WSTR + row * WSTR + m * 16,
                           d_fch + ((size_t)row << 9) + k0 + m * 8);
            }
        }
    };

    load_stage(0, 0);  CP_COMMIT();
    load_stage(1, 32); CP_COMMIT();
    load_stage(2, 64); CP_COMMIT();

    const int r = lane >> 2, c = lane & 3;

    for (int kt = 0; kt < KPW; kt++) {
        int s = kt & 3;
        asm volatile("cp.async.wait_group 2;" ::: "memory");
        __syncthreads();
        if (kt + 3 < KPW) load_stage((kt + 3) & 3, (kt + 3) * 32);
        CP_COMMIT();

        const char* Asf = smc + (size_t)s * STGW_B;
        const char* Bsf = Asf + 128 * WSTR;
#pragma unroll
        for (int kk = 0; kk < 2; kk++) {      // 2 k-steps of K=16
            uint32_t a0[2], a1[2], a2[2], a3[2];
#pragma unroll
            for (int mt = 0; mt < 2; mt++) {
                int ro = wm * 32 + mt * 16 + r;
                a0[mt] = *reinterpret_cast<const uint32_t*>(Asf + ro * WSTR + (8 * kk + c) * 4);
                a2[mt] = *reinterpret_cast<const uint32_t*>(Asf + ro * WSTR + (8 * kk + 4 + c) * 4);
                a1[mt] = *reinterpret_cast<const uint32_t*>(Asf + (ro + 8) * WSTR + (8 * kk + c) * 4);
                a3[mt] = *reinterpret_cast<const uint32_t*>(Asf + (ro + 8) * WSTR + (8 * kk + 4 + c) * 4);
            }
#pragma unroll
            for (int nt = 0; nt < 5; nt++) {
                int n = wn * 40 + nt * 8 + r;
                uint32_t b0 = *reinterpret_cast<const uint32_t*>(
                    Bsf + n * WSTR + (8 * kk + c) * 4);
                uint32_t b1 = *reinterpret_cast<const uint32_t*>(
                    Bsf + n * WSTR + (8 * kk + 4 + c) * 4);
#pragma unroll
                for (int mt = 0; mt < 2; mt++) {
                    asm volatile(
                        "mma.sync.aligned.m16n8k16.row.col.f32.f16.f16.f32 "
                        "{%0,%1,%2,%3}, {%4,%5,%6,%7}, {%8,%9}, {%0,%1,%2,%3};"
                        : "+f"(acc[mt][nt][0]), "+f"(acc[mt][nt][1]),
                          "+f"(acc[mt][nt][2]), "+f"(acc[mt][nt][3])
                        : "r"(a0[mt]), "r"(a1[mt]), "r"(a2[mt]), "r"(a3[mt]),
                          "r"(b0), "r"(b1));
                }
            }
        }
    }

    // epilogue: VTp[(80*r5 + col)][perm16(i)] = fp16(acc)
#pragma unroll
    for (int mt = 0; mt < 2; mt++) {
        int m = m0 + wm * 32 + mt * 16 + r;
        int r5 = m >> 12;
        int i1 = m & 4095;
        int i2 = i1 + 8;
        int k1 = i1 & 15, k2 = i2 & 15;
        int pos1 = (i1 & ~15) | ((((k1 & 7) >> 1) << 2) | ((k1 >> 3) << 1) | (k1 & 1));
        int pos2 = (i2 & ~15) | ((((k2 & 7) >> 1) << 2) | ((k2 >> 3) << 1) | (k2 & 1));
#pragma unroll
        for (int nt = 0; nt < 5; nt++) {
            int col = wn * 40 + nt * 8 + 2 * c;
            if (col < HH1) {
                size_t vr = (size_t)(r5 * LDS2 + col) << 12;
                d_VTp[vr + pos1] = __float2half_rn(acc[mt][nt][0]);
                d_VTp[vr + pos2] = __float2half_rn(acc[mt][nt][2]);
            }
            if (col + 1 < HH1) {
                size_t vr = (size_t)(r5 * LDS2 + col + 1) << 12;
                d_VTp[vr + pos1] = __float2half_rn(acc[mt][nt][1]);
                d_VTp[vr + pos2] = __float2half_rn(acc[mt][nt][3]);
            }
        }
    }
}

// ---------------- GEMM2 (TC fp16 m16n8k16): g2 = xp @ VTp^T ------------------
#define STG_F 6144   // floats per stage: A 16KB + B 8KB

__global__ void __launch_bounds__(128, 2) gemm2_mma() {
    extern __shared__ float sm[];
    uint32_t smb = smem_u32(sm);
    int tid = threadIdx.x;             // 128 threads
    int lane = tid & 31, wid = tid >> 5;
    int wm = wid & 1, wn = wid >> 1;   // 4 warps: 2(M) x 2(N), 64x32 each
    int m0 = blockIdx.y * 128, n0 = blockIdx.x * 64;
    const __half* Ag = d_xp + (size_t)m0 * NN;
    const __half* Bg = d_VTp + (size_t)n0 * NN;

    float acc[4][4][4];
#pragma unroll
    for (int a = 0; a < 4; a++)
#pragma unroll
        for (int b = 0; b < 4; b++)
#pragma unroll
            for (int d = 0; d < 4; d++) acc[a][b][d] = 0.f;

    auto load_stage = [&](int s, int k0) {   // k0 in halves
        uint32_t base = smb + (uint32_t)s * (STG_F * 4);
#pragma unroll
        for (int i = 0; i < 8; i++) {        // A: 128 rows x 128B
            int idx = tid + i * 128;
            int row = idx >> 3, seg = idx & 7;
            uint32_t d = base + row * 128 +
                         ((uint32_t)((2 * seg) ^ ((row & 3) << 2)) << 3);
            CP_ASYNC16(d, Ag + (size_t)row * NN + k0 + seg * 8);
        }
#pragma unroll
        for (int i = 0; i < 4; i++) {        // B: 64 rows x 128B
            int idx = tid + i * 128;
            int row = idx >> 3, seg = idx & 7;
            uint32_t d = base + 16384 + row * 128 +
                         ((uint32_t)((2 * seg) ^ ((row & 3) << 2)) << 3);
            CP_ASYNC16(d, Bg + (size_t)row * NN + k0 + seg * 8);
        }
    };

    load_stage(0, 0);   CP_COMMIT();
    load_stage(1, 64);  CP_COMMIT();
    load_stage(2, 128); CP_COMMIT();

    const int r = lane >> 2, c = lane & 3;
    const int X = (r & 3) << 2;

    for (int kt = 0; kt < KT; kt++) {
        int s = kt & 3;
        asm volatile("cp.async.wait_group 2;" ::: "memory");
        __syncthreads();
        if (kt + 3 < KT) load_stage((kt + 3) & 3, (kt + 3) * 64);
        CP_COMMIT();

        const uint2* As2 = reinterpret_cast<const uint2*>(sm + (size_t)s * STG_F);
        const uint2* Bs2 = reinterpret_cast<const uint2*>(sm + (size_t)s * STG_F + 4096);
#pragma unroll
        for (int ks = 0; ks < 4; ks++) {      // 4 k-steps of K=16
            int sl = (4 * ks) ^ X;
            uint32_t a0[4], a1[4], a2[4], a3[4];
#pragma unroll
            for (int mt = 0; mt < 4; mt++) {
                int row0 = wm * 64 + mt * 16 + r;
                uint2 lo = As2[row0 * 16 + sl + c];
                uint2 hi = As2[(row0 + 8) * 16 + sl + c];
                a0[mt] = lo.x;
                a2[mt] = lo.y;
                a1[mt] = hi.x;
                a3[mt] = hi.y;
            }
#pragma unroll
            for (int nt = 0; nt < 4; nt++) {
                int nrow = wn * 32 + nt * 8 + r;
                uint2 bb = Bs2[nrow * 16 + sl + c];
#pragma unroll
                for (int mt = 0; mt < 4; mt++) {
                    asm volatile(
                        "mma.sync.aligned.m16n8k16.row.col.f32.f16.f16.f32 "
                        "{%0,%1,%2,%3}, {%4,%5,%6,%7}, {%8,%9}, {%0,%1,%2,%3};"
                        : "+f"(acc[mt][nt][0]), "+f"(acc[mt][nt][1]),
                          "+f"(acc[mt][nt][2]), "+f"(acc[mt][nt][3])
                        : "r"(a0[mt]), "r"(a1[mt]), "r"(a2[mt]), "r"(a3[mt]),
                          "r"(bb.x), "r"(bb.y));
                }
            }
        }
    }

#pragma unroll
    for (int mt = 0; mt < 4; mt++) {
        int row = m0 + wm * 64 + mt * 16 + r;
#pragma unroll
        for (int nt = 0; nt < 4; nt++) {
            int col = n0 + wn * 32 + nt * 8 + (c << 1);
            *reinterpret_cast<float2*>(&d_g2[(size_t)row * LDG2 + col]) =
                make_float2(acc[mt][nt][0], acc[mt][nt][1]);
            *reinterpret_cast<float2*>(&d_g2[(size_t)(row + 8) * LDG2 + col]) =
                make_float2(acc[mt][nt][2], acc[mt][nt][3]);
        }
    }
}

// ---------------- aggregate: one warp per segment, no atomics -----------------
__global__ void k_agg() {
    int warp = (blockIdx.x * blockDim.x + threadIdx.x) >> 5;
    int lane = threadIdx.x & 31;
    if (warp >= NSEG) return;
    int seg = warp;
    int t = seg % RR;
    int cnt = d_hcnt[seg];
    int base = d_base[seg];

    float4 acc = make_float4(0.f, 0.f, 0.f, 0.f);
    if (lane < 19) {
        for (int k = 0; k < cnt; k++) {
            int src = __ldg(&d_eidx[base + k]);
            const float4* grow = reinterpret_cast<const float4*>(
                d_g2 + (size_t)src * LDG2 + t * LDS2);
            float4 v = __ldg(grow + lane);
            acc.x += v.x; acc.y += v.y; acc.z += v.z; acc.w += v.w;
        }
        *reinterpret_cast<float4*>(d_sums + (size_t)seg * LDS2 + lane * 4) = acc;
    }
}

// ---------------- finalize: z -> BN(75) -> relu -> out -----------------------
__global__ void k_final(float* __restrict__ out,
                        const float* __restrict__ gu, const float* __restrict__ bu,
                        const float* __restrict__ gi, const float* __restrict__ bi) {
    int n = blockIdx.x;
    int tid = threadIdx.x;   // 128
    __shared__ float red[128];

    float zval = 0.f;
    if (tid < HH1) {
        float acc = d_biasV[tid] + d_g2[(size_t)n * LDG2 + RR * LDS2 + tid];
#pragma unroll
        for (int r = 0; r < RR; r++) {
            float c = d_cnt[n * RR + r];
            acc += d_sums[((size_t)(n * RR + r)) * LDS2 + tid] / fmaxf(c, 1.0f);
        }
        zval = acc;
    }
    red[tid] = zval;
    __syncthreads();
#pragma unroll
    for (int s = 64; s > 0; s >>= 1) {
        if (tid < s) red[tid] += red[tid + s];
        __syncthreads();
    }
    float mu = red[0] * (1.0f / HH1);
    __syncthreads();
    float d = (tid < HH1) ? (zval - mu) : 0.f;
    red[tid] = d * d;
    __syncthreads();
#pragma unroll
    for (int s = 64; s > 0; s >>= 1) {
        if (tid < s) red[tid] += red[tid + s];
        __syncthreads();
    }
    float var = red[0] * (1.0f / HH1);

    float gamma, beta;
    if (n < UU) { gamma = gu[n]; beta = bu[n]; }
    else        { gamma = gi[n - UU]; beta = bi[n - UU]; }

    if (tid < HH1) {
        float y = gamma * (zval - mu) * rsqrtf(var + 1e-5f) + beta;
        out[(size_t)n * HH1 + tid] = fmaxf(y, 0.f);
    }
}

// ---------------- launch ------------------------------------------------------
extern "C" void kernel_launch(void* const* d_in, const int* in_sizes, int n_in,
                              void* d_out, int out_size) {
    const float* x     = (const float*)d_in[0];
    const float* basis = (const float*)d_in[1];
    const float* comp  = (const float*)d_in[2];
    const float* root  = (const float*)d_in[3];
    const float* bias  = (const float*)d_in[4];
    const float* fc_w  = (const float*)d_in[5];
    const float* gu    = (const float*)d_in[6];
    const float* bu    = (const float*)d_in[7];
    const float* gi    = (const float*)d_in[8];
    const float* bi    = (const float*)d_in[9];
    const unsigned int* ei = (const unsigned int*)d_in[10];
    const unsigned int* et = (const unsigned int*)d_in[11];
    float* out = (float*)d_out;

    static cudaStream_t s2 = nullptr;
    static cudaEvent_t evF = nullptr, evJ = nullptr;
    static int init_done = 0;
    if (!init_done) {
        cudaFuncSetAttribute(gemm2_mma, cudaFuncAttributeMaxDynamicSharedMemorySize,
                             4 * STG_F * 4);
        cudaFuncSetAttribute(gemmW, cudaFuncAttributeMaxDynamicSharedMemorySize,
                             4 * STGW_B);
        cudaStreamCreateWithFlags(&s2, cudaStreamNonBlocking);
        cudaEventCreateWithFlags(&evF, cudaEventDisableTiming);
        cudaEventCreateWithFlags(&evJ, cudaEventDisableTiming);
        init_done = 1;
    }

    // detect + hcnt zero (both streams depend on this)
    k_detect<<<(NSEG + 255) / 256, 256>>>(ei, et);
    cudaEventRecord(evF, 0);
    cudaStreamWaitEvent(s2, evF, 0);

    // side stream: edge sort chain (independent of GEMM pipeline)
    k_hist<<<EE / 256, 256, 0, s2>>>(ei, et);
    k_scan1<<<160, 128, 0, s2>>>();
    k_scan2<<<1, 256, 0, s2>>>();
    k_scan3<<<(NSEG + 255) / 256, 256, 0, s2>>>();
    k_scatter<<<EE / 256, 256, 0, s2>>>(ei, et);
    cudaEventRecord(evJ, s2);

    // main stream: GEMM pipeline
    k_prep<<<(NN * NN / 2) / 256, 256>>>(x, fc_w, bias);
    k_buildW<<<(NN * 125 + 255) / 256, 256>>>(basis, root, comp);
    gemmW<<<dim3(1, 6 * NN / 128), 256, 4 * STGW_B>>>();
    gemm2_mma<<<dim3(8, 32), 128, 4 * STG_F * 4>>>();

    // join: agg needs both g2 (main) and CSR (side)
    cudaStreamWaitEvent(0, evJ, 0);
    k_agg<<<NSEG / 8, 256>>>();
    k_final<<<NN, 128>>>(out, gu, bu, gi, bi);
}